// round 5
// baseline (speedup 1.0000x reference)
#include <cuda_runtime.h>
#include <cuda_bf16.h>
#include <cstdint>

#define BB 64
#define SS 512
#define DD 1024
#define HH 1024
#define TT 9
#define NC 16        // time chunks per batch
#define CL 32        // steps per chunk
#define NCHAIN (BB*NC)                      // 1024 chains
#define CPW 3                               // chains per warp
#define NWARP ((NCHAIN + CPW - 1) / CPW)    // 342

// Scratch (device globals; no allocation allowed)
__device__ float g_WeffT[TT * DD];     // SoA: [t][d]
__device__ float g_beff[TT];
__device__ float g_P[NCHAIN * 81];     // per-chunk 9x9 log-domain composite
__device__ float g_res[BB];            // per-batch (logz - score)

// ---------------------------------------------------------------------------
// Kernel 1: WeffT[t][d] = sum_h W1[d,h]*W2[h,t];  beff = b1@W2 + b2
// ---------------------------------------------------------------------------
__global__ __launch_bounds__(256) void weff_kernel(
    const float* __restrict__ W1, const float* __restrict__ b1,
    const float* __restrict__ W2, const float* __restrict__ b2)
{
    __shared__ float sW2[HH * TT];     // 36 KB
    int tid = threadIdx.x;
    for (int i = tid; i < HH * TT; i += 256) sW2[i] = W2[i];
    __syncthreads();

    int w = tid >> 5, l = tid & 31;
    bool isb = (blockIdx.x == DD / 8);
    if (isb && w > 0) return;
    int d = blockIdx.x * 8 + w;
    const float* src = isb ? b1 : (W1 + (size_t)d * HH);

    float acc[TT];
#pragma unroll
    for (int t = 0; t < TT; t++) acc[t] = 0.f;
    for (int h = l; h < HH; h += 32) {
        float a = src[h];
        const float* r = sW2 + h * TT;
#pragma unroll
        for (int t = 0; t < TT; t++) acc[t] = fmaf(a, r[t], acc[t]);
    }
#pragma unroll
    for (int t = 0; t < TT; t++)
#pragma unroll
        for (int o = 16; o; o >>= 1)
            acc[t] += __shfl_xor_sync(0xffffffffu, acc[t], o);

    if (l == 0) {
        if (isb) {
#pragma unroll
            for (int t = 0; t < TT; t++) g_beff[t] = acc[t] + b2[t];
        } else {
#pragma unroll
            for (int t = 0; t < TT; t++) g_WeffT[t * DD + d] = acc[t];
        }
    }
}

// ---------------------------------------------------------------------------
// Kernel 2: logits = input @ Weff + beff.
// 1024 blocks x 256 thr. Warp owns 4 rows; lane owns float4 at d4 = k*32+lane
// (warp = 512 contiguous bytes -> fully coalesced LDG.128). Weff SoA in smem,
// read via LDS.128. Plain fp32 FFMA.
// ---------------------------------------------------------------------------
__global__ __launch_bounds__(256) void gemv_kernel(
    const float* __restrict__ input, float* __restrict__ logits)
{
    __shared__ float sWt[TT * DD];     // 36 KB, [t][d]
    int tid = threadIdx.x;
    for (int i = tid; i < TT * DD; i += 256) sWt[i] = g_WeffT[i];
    __syncthreads();

    int w = tid >> 5, lane = tid & 31;
    int rowbase = (blockIdx.x * 8 + w) * 4;
    const float4* ip4 = (const float4*)(input + (size_t)rowbase * DD);
    const float4* sWt4 = (const float4*)sWt;

    float acc[4][TT];
#pragma unroll
    for (int r = 0; r < 4; r++)
#pragma unroll
        for (int t = 0; t < TT; t++) acc[r][t] = 0.f;

#pragma unroll 2
    for (int k = 0; k < 8; k++) {
        int d4 = (k << 5) + lane;                 // float4 index; d = d4*4
        float4 x[4];
#pragma unroll
        for (int r = 0; r < 4; r++) x[r] = ip4[(size_t)r * (DD / 4) + d4];
        float4 wv[TT];
#pragma unroll
        for (int t = 0; t < TT; t++) wv[t] = sWt4[t * (DD / 4) + d4];
#pragma unroll
        for (int r = 0; r < 4; r++)
#pragma unroll
            for (int t = 0; t < TT; t++) {
                acc[r][t] = fmaf(x[r].x, wv[t].x, acc[r][t]);
                acc[r][t] = fmaf(x[r].y, wv[t].y, acc[r][t]);
                acc[r][t] = fmaf(x[r].z, wv[t].z, acc[r][t]);
                acc[r][t] = fmaf(x[r].w, wv[t].w, acc[r][t]);
            }
    }

    // butterfly reduce each of the 36 partials across lanes
#pragma unroll
    for (int r = 0; r < 4; r++)
#pragma unroll
        for (int t = 0; t < TT; t++)
#pragma unroll
            for (int o = 16; o; o >>= 1)
                acc[r][t] += __shfl_xor_sync(0xffffffffu, acc[r][t], o);

    if (lane < 4) {
        float* o = logits + (size_t)(rowbase + lane) * TT;
#pragma unroll
        for (int t = 0; t < TT; t++) o[t] = acc[lane][t] + g_beff[t];
    }
}

// ---------------------------------------------------------------------------
// Kernel 3: chunk composites, 3 chains per warp (lanes 0..26 in 9-lane groups).
// Linear-domain chain, group-max renorm every 8 steps. grid 43 x 256 thr.
// ---------------------------------------------------------------------------
__global__ __launch_bounds__(256) void crf_chunk_kernel(
    const float* __restrict__ logits, const int* __restrict__ mask,
    const float* __restrict__ trans)
{
    __shared__ float s_em[8][CPW][CL * TT];
    __shared__ int   s_mk[8][CPW][CL];

    int w = threadIdx.x >> 5, l = threadIdx.x & 31;
    int wg = blockIdx.x * 8 + w;
    if (wg >= NWARP) return;

    // cooperative load of this warp's 3 chains
    for (int i = l; i < CPW * CL * TT; i += 32) {
        int ch = i / (CL * TT), off = i % (CL * TT);
        int n = wg * CPW + ch;
        float v = 0.f;
        if (n < NCHAIN) {
            int b = n >> 4, c = n & 15;
            int t = 1 + c * CL + off / TT;
            if (t < SS) v = logits[((size_t)b * SS + t) * TT + off % TT];
        }
        s_em[w][ch][off] = v;
    }
    for (int i = l; i < CPW * CL; i += 32) {
        int ch = i / CL, s = i % CL;
        int n = wg * CPW + ch;
        int mv = 0;
        if (n < NCHAIN) {
            int b = n >> 4, c = n & 15;
            int t = 1 + c * CL + s;
            if (t < SS) mv = mask[(size_t)b * SS + t];
        }
        s_mk[w][ch][s] = mv;
    }
    __syncwarp();

    int g = (l < 27) ? (l / TT) : 2;       // chain group within warp
    int j = l - g * TT;                    // column 0..8 (garbage for l>=27)
    bool act = (l < 27) && (j < TT) && (wg * CPW + g < NCHAIN);
    int gbase = g * TT;

    float E[TT];
#pragma unroll
    for (int k = 0; k < TT; k++)
        E[k] = act ? __expf(trans[k * TT + j]) : 0.f;

    float R[TT], Ms[TT];
#pragma unroll
    for (int i = 0; i < TT; i++) { R[i] = (act && i == j) ? 1.f : 0.f; Ms[i] = 0.f; }

    const float* em = s_em[w][g];
    const int*   mk = s_mk[w][g];

    for (int s = 0; s < CL; s++) {
        int m = mk[s];
        float eem = __expf(act ? em[s * TT + j] : 0.f);
#pragma unroll
        for (int i = 0; i < TT; i++) {
            float v = R[i];
            float sum = 0.f;
#pragma unroll
            for (int k = 0; k < TT; k++)
                sum = fmaf(__shfl_sync(0xffffffffu, v, gbase + k), E[k], sum);
            R[i] = (m != 0) ? sum * eem : R[i];
        }
        if ((s & 7) == 7) {                // renorm by diagonal (positive)
#pragma unroll
            for (int i = 0; i < TT; i++) {
                float sc = __shfl_sync(0xffffffffu, R[i], gbase + i);
                float r = __fdividef(1.f, sc);
                R[i] *= r;
                Ms[i] += __logf(sc);
            }
        }
    }
    if (act) {
        int n = wg * CPW + g;
        float* Pp = g_P + (size_t)n * 81;
#pragma unroll
        for (int i = 0; i < TT; i++) Pp[i * TT + j] = Ms[i] + __logf(R[i]);
    }
}

// ---------------------------------------------------------------------------
// Kernel 4: per-batch combine. Block of 256 threads per batch.
// Tree of 9x9 log-semiring products (4 levels), + numerator + logz.
// ---------------------------------------------------------------------------
__global__ __launch_bounds__(256) void crf_combine_kernel(
    const float* __restrict__ logits, const int* __restrict__ labels,
    const int* __restrict__ mask, const float* __restrict__ start,
    const float* __restrict__ endt, const float* __restrict__ trans)
{
    __shared__ float sP[NC * 108];     // matrix c at c*108, entry [i][j] at i*12+j
    __shared__ int   s_mk[SS];
    __shared__ int   s_tg[SS];
    __shared__ float s_red[256];
    __shared__ int   s_ridx[256];
    __shared__ float s_alpha[TT];
    __shared__ float s_score;

    int b = blockIdx.x, tid = threadIdx.x;

    const float* Pb = g_P + (size_t)b * NC * 81;
    for (int i = tid; i < NC * 81; i += 256) {
        int c = i / 81, r = i % 81;
        sP[c * 108 + (r / TT) * 12 + r % TT] = Pb[i];
    }
    for (int i = tid; i < SS; i += 256) {
        s_mk[i] = mask[(size_t)b * SS + i];
        s_tg[i] = labels[(size_t)b * SS + i];
    }
    __syncthreads();

    // ---- numerator partial + last-masked-index (each thread: t, t+256) ----
    float contrib = 0.f;
    int ridx = 0;
#pragma unroll
    for (int h = 0; h < 2; h++) {
        int t = tid + h * 256;
        if (t == 0) {
            contrib += start[s_tg[0]] + logits[(size_t)b * SS * TT + s_tg[0]];
        } else if (s_mk[t] > 0) {
            int tp = t - 1;
            while (tp > 0 && s_mk[tp] == 0) tp--;
            contrib += trans[s_tg[tp] * TT + s_tg[t]]
                     + logits[((size_t)b * SS + t) * TT + s_tg[t]];
            ridx = max(ridx, t);
        }
    }
    s_red[tid] = contrib;
    s_ridx[tid] = ridx;
    __syncthreads();
#pragma unroll
    for (int o = 128; o; o >>= 1) {
        if (tid < o) {
            s_red[tid] += s_red[tid + o];
            s_ridx[tid] = max(s_ridx[tid], s_ridx[tid + o]);
        }
        __syncthreads();
    }
    if (tid == 0) s_score = s_red[0] + endt[s_tg[s_ridx[0]]];

    // ---- tree combine: 4 levels; level L: (8>>L) warps, stride 1<<L ----
    int w = tid >> 5, lane = tid & 31;
#pragma unroll
    for (int L = 0; L < 4; L++) {
        __syncthreads();
        int nprod = 8 >> L, stride = 1 << L;
        if (w < nprod && lane < TT) {
            int a = (w * 2) * stride, bb2 = a + stride;
            const float* A = sP + a * 108;
            const float* Bc = sP + bb2 * 108;
            float Bcol[TT];
#pragma unroll
            for (int k = 0; k < TT; k++) Bcol[k] = Bc[k * 12 + lane];
            float C[TT];
#pragma unroll
            for (int i = 0; i < TT; i++) {
                float vmax = -1e30f;
                float vv[TT];
#pragma unroll
                for (int k = 0; k < TT; k++) {
                    vv[k] = A[i * 12 + k] + Bcol[k];
                    vmax = fmaxf(vmax, vv[k]);
                }
                float ssum = 0.f;
#pragma unroll
                for (int k = 0; k < TT; k++) ssum += __expf(vv[k] - vmax);
                C[i] = vmax + __logf(ssum);
            }
            float* Cs = sP + a * 108;
#pragma unroll
            for (int i = 0; i < TT; i++) Cs[i * 12 + lane] = C[i];
        }
    }
    __syncthreads();

    // ---- final: alpha0 (x) P, logz, result ----
    if (w == 0) {
        if (lane < TT)
            s_alpha[lane] = start[lane] + logits[(size_t)b * SS * TT + lane];
        __syncwarp();
        float v = -1e30f;
        if (lane < TT) {
            float vmax = -1e30f, vv[TT];
#pragma unroll
            for (int i = 0; i < TT; i++) {
                vv[i] = s_alpha[i] + sP[i * 12 + lane];
                vmax = fmaxf(vmax, vv[i]);
            }
            float ssum = 0.f;
#pragma unroll
            for (int i = 0; i < TT; i++) ssum += __expf(vv[i] - vmax);
            v = vmax + __logf(ssum) + endt[lane];
        }
        float Mx = v;
#pragma unroll
        for (int o = 16; o; o >>= 1) Mx = fmaxf(Mx, __shfl_xor_sync(0xffffffffu, Mx, o));
        float e = __expf(v - Mx);
#pragma unroll
        for (int o = 16; o; o >>= 1) e += __shfl_xor_sync(0xffffffffu, e, o);
        if (lane == 0) g_res[b] = (Mx + __logf(e)) - s_score;
    }
}

// ---------------------------------------------------------------------------
// Kernel 5: loss = mean(res), fixed-order reduce
// ---------------------------------------------------------------------------
__global__ __launch_bounds__(64) void final_kernel(float* __restrict__ out)
{
    __shared__ float sv[BB];
    int t = threadIdx.x;
    sv[t] = g_res[t];
    __syncthreads();
#pragma unroll
    for (int o = 32; o; o >>= 1) {
        if (t < o) sv[t] += sv[t + o];
        __syncthreads();
    }
    if (t == 0) out[0] = sv[0] * (1.0f / 64.0f);
}

// ---------------------------------------------------------------------------
extern "C" void kernel_launch(void* const* d_in, const int* in_sizes, int n_in,
                              void* d_out, int out_size)
{
    const float* input  = (const float*)d_in[0];
    const int*   labels = (const int*)  d_in[1];
    const int*   mask   = (const int*)  d_in[2];
    const float* W1     = (const float*)d_in[3];
    const float* b1     = (const float*)d_in[4];
    const float* W2     = (const float*)d_in[5];
    const float* b2     = (const float*)d_in[6];
    const float* start  = (const float*)d_in[7];
    const float* endt   = (const float*)d_in[8];
    const float* trans  = (const float*)d_in[9];

    float* out    = (float*)d_out;
    float* logits = out + 1;   // output layout: [loss, logits(B,S,T)]

    weff_kernel<<<DD / 8 + 1, 256>>>(W1, b1, W2, b2);
    gemv_kernel<<<1024, 256>>>(input, logits);
    crf_chunk_kernel<<<(NWARP + 7) / 8, 256>>>(logits, mask, trans);
    crf_combine_kernel<<<BB, 256>>>(logits, labels, mask, start, endt, trans);
    final_kernel<<<1, BB>>>(out);
}

// round 6
// speedup vs baseline: 1.4318x; 1.4318x over previous
#include <cuda_runtime.h>
#include <cuda_bf16.h>
#include <cstdint>

#define BB 64
#define SS 512
#define DD 1024
#define HH 1024
#define TT 9
#define NC 16        // time chunks per batch (chunk c = steps [32c, 32c+31], chunk0 = 1..31)

// Scratch (device globals; no allocation allowed)
__device__ float g_WeffT[TT * DD];     // SoA: [t][d]
__device__ float g_beff[TT];
__device__ float g_P[BB * NC * 81];    // per-chunk 9x9 log-domain composite
__device__ float g_res[BB];            // per-batch (logz - score)

// ---------------------------------------------------------------------------
// Kernel 1: WeffT[t][d] = sum_h W1[d,h]*W2[h,t];  beff = b1@W2 + b2
// ---------------------------------------------------------------------------
__global__ __launch_bounds__(256) void weff_kernel(
    const float* __restrict__ W1, const float* __restrict__ b1,
    const float* __restrict__ W2, const float* __restrict__ b2)
{
    __shared__ float sW2[HH * TT];     // 36 KB
    int tid = threadIdx.x;
    for (int i = tid; i < HH * TT; i += 256) sW2[i] = W2[i];
    __syncthreads();

    int w = tid >> 5, l = tid & 31;
    bool isb = (blockIdx.x == DD / 8);
    if (isb && w > 0) return;
    int d = blockIdx.x * 8 + w;
    const float* src = isb ? b1 : (W1 + (size_t)d * HH);

    float acc[TT];
#pragma unroll
    for (int t = 0; t < TT; t++) acc[t] = 0.f;
    for (int h = l; h < HH; h += 32) {
        float a = src[h];
        const float* r = sW2 + h * TT;
#pragma unroll
        for (int t = 0; t < TT; t++) acc[t] = fmaf(a, r[t], acc[t]);
    }
#pragma unroll
    for (int t = 0; t < TT; t++)
#pragma unroll
        for (int o = 16; o; o >>= 1)
            acc[t] += __shfl_xor_sync(0xffffffffu, acc[t], o);

    if (l == 0) {
        if (isb) {
#pragma unroll
            for (int t = 0; t < TT; t++) g_beff[t] = acc[t] + b2[t];
        } else {
#pragma unroll
            for (int t = 0; t < TT; t++) g_WeffT[t * DD + d] = acc[t];
        }
    }
}

// ---------------------------------------------------------------------------
// Kernel 2 (fused): logits tile + chunk composite.
// 1024 blocks (= 64 batches x 16 chunks) x 256 thr. Block computes its 32
// rows of logits (R4-proven coalesced scalar path), keeps them in smem, then:
//   - each warp w builds the 4-step linear-domain composite of steps
//     t = 32c+4w .. 32c+4w+3 (chunk 0 warp 0: steps 1..3)
//   - 3-level tree of 9x9 products in smem (max-renorm each level)
//   - writes the chunk's 9x9 log-domain composite to g_P.
// ---------------------------------------------------------------------------
__global__ __launch_bounds__(256) void gemv_chunk_kernel(
    const float* __restrict__ input, float* __restrict__ logits,
    const int* __restrict__ mask, const float* __restrict__ trans)
{
    __shared__ float sWt[TT * DD];       // 36 KB, [t][d]
    __shared__ float s_lg[32][TT];       // this block's 32 logit rows
    __shared__ int   s_mk[32];
    __shared__ float sM[8][TT][12];      // per-warp composites (padded)
    __shared__ float sSc[8];             // per-warp log-scales

    int tid = threadIdx.x;
    for (int i = tid; i < TT * DD; i += 256) sWt[i] = g_WeffT[i];

    int b = blockIdx.x >> 4;             // batch
    int c = blockIdx.x & 15;             // chunk
    if (tid < 32) s_mk[tid] = mask[(size_t)b * SS + c * 32 + tid];
    __syncthreads();

    int w = tid >> 5, lane = tid & 31;
    int rowbase = blockIdx.x * 32 + w * 4;
    const float* ip = input + (size_t)rowbase * DD;

    float acc[4][TT];
#pragma unroll
    for (int r = 0; r < 4; r++)
#pragma unroll
        for (int t = 0; t < TT; t++) acc[r][t] = 0.f;

#pragma unroll 2
    for (int k = 0; k < 32; k++) {
        int d = (k << 5) + lane;
        float x[4];
#pragma unroll
        for (int r = 0; r < 4; r++) x[r] = ip[(size_t)r * DD + d];  // coalesced
        float wv[TT];
#pragma unroll
        for (int t = 0; t < TT; t++) wv[t] = sWt[t * DD + d];       // stride-1 LDS
#pragma unroll
        for (int r = 0; r < 4; r++)
#pragma unroll
            for (int t = 0; t < TT; t++)
                acc[r][t] = fmaf(x[r], wv[t], acc[r][t]);
    }

#pragma unroll
    for (int r = 0; r < 4; r++)
#pragma unroll
        for (int t = 0; t < TT; t++)
#pragma unroll
            for (int o = 16; o; o >>= 1)
                acc[r][t] += __shfl_xor_sync(0xffffffffu, acc[r][t], o);

    if (lane < 4) {
        int rl = w * 4 + lane;
        float* o = logits + (size_t)(rowbase + lane) * TT;
#pragma unroll
        for (int t = 0; t < TT; t++) {
            float v = acc[lane][t] + g_beff[t];
            o[t] = v;
            s_lg[rl][t] = v;
        }
    }
    __syncthreads();

    // ================= chunk composite =================
    bool act = (lane < TT);
    float E[TT];
#pragma unroll
    for (int k = 0; k < TT; k++)
        E[k] = act ? __expf(trans[k * TT + lane]) : 0.f;

    int ls0 = w * 4;
    int sfirst = (c == 0 && w == 0) ? 1 : 0;     // skip global t = 0

    float R[TT];
    {   // init from first step (or identity if masked)
        int ls = ls0 + sfirst;
        bool mm = (s_mk[ls] != 0);
        float eem = act ? __expf(s_lg[ls][lane]) : 0.f;
#pragma unroll
        for (int i = 0; i < TT; i++)
            R[i] = mm ? E[i] * eem : ((act && i == lane) ? 1.f : 0.f);
    }
#pragma unroll
    for (int q = 1; q < 4; q++) {
        int ls = ls0 + ((sfirst) ? (q + 1) : q);
        if (ls >= ls0 + 4) break;                // only when sfirst==1: 3 steps
        if (s_mk[ls] != 0) {
            float eem = act ? __expf(s_lg[ls][lane]) : 0.f;
#pragma unroll
            for (int i = 0; i < TT; i++) {
                float v = R[i];
                float sum = 0.f;
#pragma unroll
                for (int k = 0; k < TT; k++)
                    sum = fmaf(__shfl_sync(0xffffffffu, v, k), E[k], sum);
                R[i] = sum * eem;
            }
        }
    }
    // per-warp renorm + store
    {
        float mx = 1e-38f;
#pragma unroll
        for (int i = 0; i < TT; i++) mx = fmaxf(mx, R[i]);
        float gm = 1e-38f;
#pragma unroll
        for (int k = 0; k < TT; k++)
            gm = fmaxf(gm, __shfl_sync(0xffffffffu, mx, k));
        float inv = __fdividef(1.f, gm);
        if (act) {
#pragma unroll
            for (int i = 0; i < TT; i++) sM[w][i][lane] = R[i] * inv;
        }
        if (lane == 0) sSc[w] = __logf(gm);
    }
    __syncthreads();

    // tree: 3 levels of linear 9x9 products (A earlier, B later)
#pragma unroll
    for (int L = 0; L < 3; L++) {
        int stride = 1 << L, npr = 4 >> L;
        if (w < npr) {
            int a = 2 * stride * w, bq = a + stride;
            float Bcol[TT];
#pragma unroll
            for (int k = 0; k < TT; k++) Bcol[k] = act ? sM[bq][k][lane] : 0.f;
            float C[TT];
            float mx = 1e-38f;
#pragma unroll
            for (int i = 0; i < TT; i++) {
                float s = 0.f;
#pragma unroll
                for (int k = 0; k < TT; k++)
                    s = fmaf(sM[a][i][k], Bcol[k], s);   // A broadcast-LDS
                C[i] = s;
                mx = fmaxf(mx, s);
            }
            float gm = 1e-38f;
#pragma unroll
            for (int k = 0; k < TT; k++)
                gm = fmaxf(gm, __shfl_sync(0xffffffffu, mx, k));
            float inv = __fdividef(1.f, gm);
            float addsc = sSc[bq] + __logf(gm);
            __syncwarp();
            if (act) {
#pragma unroll
                for (int i = 0; i < TT; i++) sM[a][i][lane] = C[i] * inv;
            }
            if (lane == 0) sSc[a] += addsc;
        }
        __syncthreads();
    }

    if (w == 0 && act) {
        float sc = sSc[0];
        float* Pp = g_P + (size_t)blockIdx.x * 81;
#pragma unroll
        for (int i = 0; i < TT; i++)
            Pp[i * TT + lane] = __logf(fmaxf(sM[0][i][lane], 1e-38f)) + sc;
    }
}

// ---------------------------------------------------------------------------
// Kernel 3: per-batch combine (R4-proven). Block of 256 threads per batch.
// Tree of 9x9 log-semiring products (4 levels), + numerator + logz.
// ---------------------------------------------------------------------------
__global__ __launch_bounds__(256) void crf_combine_kernel(
    const float* __restrict__ logits, const int* __restrict__ labels,
    const int* __restrict__ mask, const float* __restrict__ start,
    const float* __restrict__ endt, const float* __restrict__ trans)
{
    __shared__ float sP[NC * 108];     // matrix c at c*108, entry [i][j] at i*12+j
    __shared__ int   s_mk[SS];
    __shared__ int   s_tg[SS];
    __shared__ float s_red[256];
    __shared__ int   s_ridx[256];
    __shared__ float s_alpha[TT];
    __shared__ float s_score;

    int b = blockIdx.x, tid = threadIdx.x;

    const float* Pb = g_P + (size_t)b * NC * 81;
    for (int i = tid; i < NC * 81; i += 256) {
        int c = i / 81, r = i % 81;
        sP[c * 108 + (r / TT) * 12 + r % TT] = Pb[i];
    }
    for (int i = tid; i < SS; i += 256) {
        s_mk[i] = mask[(size_t)b * SS + i];
        s_tg[i] = labels[(size_t)b * SS + i];
    }
    __syncthreads();

    // ---- numerator partial + last-masked-index (each thread: t, t+256) ----
    float contrib = 0.f;
    int ridx = 0;
#pragma unroll
    for (int h = 0; h < 2; h++) {
        int t = tid + h * 256;
        if (t == 0) {
            contrib += start[s_tg[0]] + logits[(size_t)b * SS * TT + s_tg[0]];
        } else if (s_mk[t] > 0) {
            int tp = t - 1;
            while (tp > 0 && s_mk[tp] == 0) tp--;
            contrib += trans[s_tg[tp] * TT + s_tg[t]]
                     + logits[((size_t)b * SS + t) * TT + s_tg[t]];
            ridx = max(ridx, t);
        }
    }
    s_red[tid] = contrib;
    s_ridx[tid] = ridx;
    __syncthreads();
#pragma unroll
    for (int o = 128; o; o >>= 1) {
        if (tid < o) {
            s_red[tid] += s_red[tid + o];
            s_ridx[tid] = max(s_ridx[tid], s_ridx[tid + o]);
        }
        __syncthreads();
    }
    if (tid == 0) s_score = s_red[0] + endt[s_tg[s_ridx[0]]];

    // ---- tree combine: 4 levels ----
    int w = tid >> 5, lane = tid & 31;
#pragma unroll
    for (int L = 0; L < 4; L++) {
        __syncthreads();
        int nprod = 8 >> L, stride = 1 << L;
        if (w < nprod && lane < TT) {
            int a = (w * 2) * stride, bb2 = a + stride;
            const float* A = sP + a * 108;
            const float* Bc = sP + bb2 * 108;
            float Bcol[TT];
#pragma unroll
            for (int k = 0; k < TT; k++) Bcol[k] = Bc[k * 12 + lane];
            float C[TT];
#pragma unroll
            for (int i = 0; i < TT; i++) {
                float vmax = -1e30f;
                float vv[TT];
#pragma unroll
                for (int k = 0; k < TT; k++) {
                    vv[k] = A[i * 12 + k] + Bcol[k];
                    vmax = fmaxf(vmax, vv[k]);
                }
                float ssum = 0.f;
#pragma unroll
                for (int k = 0; k < TT; k++) ssum += __expf(vv[k] - vmax);
                C[i] = vmax + __logf(ssum);
            }
            float* Cs = sP + a * 108;
#pragma unroll
            for (int i = 0; i < TT; i++) Cs[i * 12 + lane] = C[i];
        }
    }
    __syncthreads();

    // ---- final: alpha0 (x) P, logz, result ----
    if (w == 0) {
        if (lane < TT)
            s_alpha[lane] = start[lane] + logits[(size_t)b * SS * TT + lane];
        __syncwarp();
        float v = -1e30f;
        if (lane < TT) {
            float vmax = -1e30f, vv[TT];
#pragma unroll
            for (int i = 0; i < TT; i++) {
                vv[i] = s_alpha[i] + sP[i * 12 + lane];
                vmax = fmaxf(vmax, vv[i]);
            }
            float ssum = 0.f;
#pragma unroll
            for (int i = 0; i < TT; i++) ssum += __expf(vv[i] - vmax);
            v = vmax + __logf(ssum) + endt[lane];
        }
        float Mx = v;
#pragma unroll
        for (int o = 16; o; o >>= 1) Mx = fmaxf(Mx, __shfl_xor_sync(0xffffffffu, Mx, o));
        float e = __expf(v - Mx);
#pragma unroll
        for (int o = 16; o; o >>= 1) e += __shfl_xor_sync(0xffffffffu, e, o);
        if (lane == 0) g_res[b] = (Mx + __logf(e)) - s_score;
    }
}

// ---------------------------------------------------------------------------
// Kernel 4: loss = mean(res), fixed-order reduce
// ---------------------------------------------------------------------------
__global__ __launch_bounds__(64) void final_kernel(float* __restrict__ out)
{
    __shared__ float sv[BB];
    int t = threadIdx.x;
    sv[t] = g_res[t];
    __syncthreads();
#pragma unroll
    for (int o = 32; o; o >>= 1) {
        if (t < o) sv[t] += sv[t + o];
        __syncthreads();
    }
    if (t == 0) out[0] = sv[0] * (1.0f / 64.0f);
}

// ---------------------------------------------------------------------------
extern "C" void kernel_launch(void* const* d_in, const int* in_sizes, int n_in,
                              void* d_out, int out_size)
{
    const float* input  = (const float*)d_in[0];
    const int*   labels = (const int*)  d_in[1];
    const int*   mask   = (const int*)  d_in[2];
    const float* W1     = (const float*)d_in[3];
    const float* b1     = (const float*)d_in[4];
    const float* W2     = (const float*)d_in[5];
    const float* b2     = (const float*)d_in[6];
    const float* start  = (const float*)d_in[7];
    const float* endt   = (const float*)d_in[8];
    const float* trans  = (const float*)d_in[9];

    float* out    = (float*)d_out;
    float* logits = out + 1;   // output layout: [loss, logits(B,S,T)]

    weff_kernel<<<DD / 8 + 1, 256>>>(W1, b1, W2, b2);
    gemv_chunk_kernel<<<BB * NC, 256>>>(input, logits, mask, trans);
    crf_combine_kernel<<<BB, 256>>>(logits, labels, mask, start, endt, trans);
    final_kernel<<<1, BB>>>(out);
}

// round 7
// speedup vs baseline: 1.4641x; 1.0225x over previous
#include <cuda_runtime.h>
#include <cuda_bf16.h>
#include <cstdint>

#define BB 64
#define SS 512
#define DD 1024
#define HH 1024
#define TT 9
#define NC 16        // time chunks per batch (chunk c = steps [32c, 32c+31], chunk0 = 1..31)

// Scratch (device globals; no allocation allowed)
__device__ float g_WeffT[TT * DD];     // SoA: [t][d]
__device__ float g_beff[TT];
__device__ float g_P[BB * NC * 81];    // per-chunk 9x9 log-domain composite
__device__ float g_res[BB];            // per-batch (logz - score)
__device__ unsigned g_count;           // combine completion ticket (resets to 0)

// ---------------------------------------------------------------------------
// Kernel 1: WeffT[t][d] = sum_h W1[d,h]*W2[h,t];  beff = b1@W2 + b2
// ---------------------------------------------------------------------------
__global__ __launch_bounds__(256) void weff_kernel(
    const float* __restrict__ W1, const float* __restrict__ b1,
    const float* __restrict__ W2, const float* __restrict__ b2)
{
    __shared__ float sW2[HH * TT];     // 36 KB
    int tid = threadIdx.x;
    for (int i = tid; i < HH * TT; i += 256) sW2[i] = W2[i];
    __syncthreads();

    int w = tid >> 5, l = tid & 31;
    bool isb = (blockIdx.x == DD / 8);
    if (isb && w > 0) return;
    int d = blockIdx.x * 8 + w;
    const float* src = isb ? b1 : (W1 + (size_t)d * HH);

    float acc[TT];
#pragma unroll
    for (int t = 0; t < TT; t++) acc[t] = 0.f;
    for (int h = l; h < HH; h += 32) {
        float a = src[h];
        const float* r = sW2 + h * TT;
#pragma unroll
        for (int t = 0; t < TT; t++) acc[t] = fmaf(a, r[t], acc[t]);
    }
#pragma unroll
    for (int t = 0; t < TT; t++)
#pragma unroll
        for (int o = 16; o; o >>= 1)
            acc[t] += __shfl_xor_sync(0xffffffffu, acc[t], o);

    if (l == 0) {
        if (isb) {
#pragma unroll
            for (int t = 0; t < TT; t++) g_beff[t] = acc[t] + b2[t];
        } else {
#pragma unroll
            for (int t = 0; t < TT; t++) g_WeffT[t * DD + d] = acc[t];
        }
    }
}

// ---------------------------------------------------------------------------
// Kernel 2 (fused): logits tile + chunk composite (unchanged from R6).
// ---------------------------------------------------------------------------
__global__ __launch_bounds__(256) void gemv_chunk_kernel(
    const float* __restrict__ input, float* __restrict__ logits,
    const int* __restrict__ mask, const float* __restrict__ trans)
{
    __shared__ float sWt[TT * DD];       // 36 KB, [t][d]
    __shared__ float s_lg[32][TT];       // this block's 32 logit rows
    __shared__ int   s_mk[32];
    __shared__ float sM[8][TT][12];      // per-warp composites (padded)
    __shared__ float sSc[8];             // per-warp log-scales

    int tid = threadIdx.x;
    for (int i = tid; i < TT * DD; i += 256) sWt[i] = g_WeffT[i];

    int b = blockIdx.x >> 4;             // batch
    int c = blockIdx.x & 15;             // chunk
    if (tid < 32) s_mk[tid] = mask[(size_t)b * SS + c * 32 + tid];
    __syncthreads();

    int w = tid >> 5, lane = tid & 31;
    int rowbase = blockIdx.x * 32 + w * 4;
    const float* ip = input + (size_t)rowbase * DD;

    float acc[4][TT];
#pragma unroll
    for (int r = 0; r < 4; r++)
#pragma unroll
        for (int t = 0; t < TT; t++) acc[r][t] = 0.f;

#pragma unroll 2
    for (int k = 0; k < 32; k++) {
        int d = (k << 5) + lane;
        float x[4];
#pragma unroll
        for (int r = 0; r < 4; r++) x[r] = ip[(size_t)r * DD + d];  // coalesced
        float wv[TT];
#pragma unroll
        for (int t = 0; t < TT; t++) wv[t] = sWt[t * DD + d];       // stride-1 LDS
#pragma unroll
        for (int r = 0; r < 4; r++)
#pragma unroll
            for (int t = 0; t < TT; t++)
                acc[r][t] = fmaf(x[r], wv[t], acc[r][t]);
    }

#pragma unroll
    for (int r = 0; r < 4; r++)
#pragma unroll
        for (int t = 0; t < TT; t++)
#pragma unroll
            for (int o = 16; o; o >>= 1)
                acc[r][t] += __shfl_xor_sync(0xffffffffu, acc[r][t], o);

    if (lane < 4) {
        int rl = w * 4 + lane;
        float* o = logits + (size_t)(rowbase + lane) * TT;
#pragma unroll
        for (int t = 0; t < TT; t++) {
            float v = acc[lane][t] + g_beff[t];
            o[t] = v;
            s_lg[rl][t] = v;
        }
    }
    __syncthreads();

    // ================= chunk composite =================
    bool act = (lane < TT);
    float E[TT];
#pragma unroll
    for (int k = 0; k < TT; k++)
        E[k] = act ? __expf(trans[k * TT + lane]) : 0.f;

    int ls0 = w * 4;
    int sfirst = (c == 0 && w == 0) ? 1 : 0;     // skip global t = 0

    float R[TT];
    {   // init from first step (or identity if masked)
        int ls = ls0 + sfirst;
        bool mm = (s_mk[ls] != 0);
        float eem = act ? __expf(s_lg[ls][lane]) : 0.f;
#pragma unroll
        for (int i = 0; i < TT; i++)
            R[i] = mm ? E[i] * eem : ((act && i == lane) ? 1.f : 0.f);
    }
#pragma unroll
    for (int q = 1; q < 4; q++) {
        int ls = ls0 + ((sfirst) ? (q + 1) : q);
        if (ls >= ls0 + 4) break;                // only when sfirst==1: 3 steps
        if (s_mk[ls] != 0) {
            float eem = act ? __expf(s_lg[ls][lane]) : 0.f;
#pragma unroll
            for (int i = 0; i < TT; i++) {
                float v = R[i];
                float sum = 0.f;
#pragma unroll
                for (int k = 0; k < TT; k++)
                    sum = fmaf(__shfl_sync(0xffffffffu, v, k), E[k], sum);
                R[i] = sum * eem;
            }
        }
    }
    // per-warp renorm + store
    {
        float mx = 1e-38f;
#pragma unroll
        for (int i = 0; i < TT; i++) mx = fmaxf(mx, R[i]);
        float gm = 1e-38f;
#pragma unroll
        for (int k = 0; k < TT; k++)
            gm = fmaxf(gm, __shfl_sync(0xffffffffu, mx, k));
        float inv = __fdividef(1.f, gm);
        if (act) {
#pragma unroll
            for (int i = 0; i < TT; i++) sM[w][i][lane] = R[i] * inv;
        }
        if (lane == 0) sSc[w] = __logf(gm);
    }
    __syncthreads();

    // tree: 3 levels of linear 9x9 products (A earlier, B later)
#pragma unroll
    for (int L = 0; L < 3; L++) {
        int stride = 1 << L, npr = 4 >> L;
        if (w < npr) {
            int a = 2 * stride * w, bq = a + stride;
            float Bcol[TT];
#pragma unroll
            for (int k = 0; k < TT; k++) Bcol[k] = act ? sM[bq][k][lane] : 0.f;
            float C[TT];
            float mx = 1e-38f;
#pragma unroll
            for (int i = 0; i < TT; i++) {
                float s = 0.f;
#pragma unroll
                for (int k = 0; k < TT; k++)
                    s = fmaf(sM[a][i][k], Bcol[k], s);   // A broadcast-LDS
                C[i] = s;
                mx = fmaxf(mx, s);
            }
            float gm = 1e-38f;
#pragma unroll
            for (int k = 0; k < TT; k++)
                gm = fmaxf(gm, __shfl_sync(0xffffffffu, mx, k));
            float inv = __fdividef(1.f, gm);
            float addsc = sSc[bq] + __logf(gm);
            __syncwarp();
            if (act) {
#pragma unroll
                for (int i = 0; i < TT; i++) sM[a][i][lane] = C[i] * inv;
            }
            if (lane == 0) sSc[a] += addsc;
        }
        __syncthreads();
    }

    if (w == 0 && act) {
        float sc = sSc[0];
        float* Pp = g_P + (size_t)blockIdx.x * 81;
#pragma unroll
        for (int i = 0; i < TT; i++)
            Pp[i * TT + lane] = __logf(fmaxf(sM[0][i][lane], 1e-38f)) + sc;
    }
}

// ---------------------------------------------------------------------------
// Kernel 3: per-batch combine, LINEAR-domain tree + fused final reduce.
// 64 blocks x 256 thr. Chunk matrices converted log->linear once (max-renorm),
// tree of 4 levels of 81-FFMA products, alpha0/logz also linear. Last block
// (atomic ticket) sums g_res in fixed order and writes the loss.
// ---------------------------------------------------------------------------
__global__ __launch_bounds__(256) void crf_combine_kernel(
    const float* __restrict__ logits, const int* __restrict__ labels,
    const int* __restrict__ mask, const float* __restrict__ start,
    const float* __restrict__ endt, const float* __restrict__ trans,
    float* __restrict__ out)
{
    __shared__ float sM[NC][TT][12];   // linear matrices (padded cols)
    __shared__ float sSc[NC];          // per-matrix log scales
    __shared__ int   s_mk[SS];
    __shared__ int   s_tg[SS];
    __shared__ float s_red[256];
    __shared__ int   s_ridx[256];
    __shared__ float s_score;

    int b = blockIdx.x, tid = threadIdx.x;
    int w = tid >> 5, lane = tid & 31;
    bool act = (lane < TT);

    for (int i = tid; i < SS; i += 256) {
        s_mk[i] = mask[(size_t)b * SS + i];
        s_tg[i] = labels[(size_t)b * SS + i];
    }

    // ---- load chunk matrices, convert to linear with per-matrix renorm ----
    const float* Pb = g_P + (size_t)b * NC * 81;
#pragma unroll
    for (int h = 0; h < 2; h++) {
        int m = w * 2 + h;
        const float* Pm = Pb + m * 81;
        float col[TT];
        float mx = -1e30f;
#pragma unroll
        for (int i = 0; i < TT; i++) {
            col[i] = act ? Pm[i * TT + lane] : -1e30f;
            mx = fmaxf(mx, col[i]);
        }
        float gm = mx;
#pragma unroll
        for (int o = 16; o; o >>= 1)
            gm = fmaxf(gm, __shfl_xor_sync(0xffffffffu, gm, o));
        if (act) {
#pragma unroll
            for (int i = 0; i < TT; i++) sM[m][i][lane] = __expf(col[i] - gm);
        }
        if (lane == 0) sSc[m] = gm;
    }
    __syncthreads();

    // ---- numerator partial + last-masked-index (each thread: t, t+256) ----
    float contrib = 0.f;
    int ridx = 0;
#pragma unroll
    for (int h = 0; h < 2; h++) {
        int t = tid + h * 256;
        if (t == 0) {
            contrib += start[s_tg[0]] + logits[(size_t)b * SS * TT + s_tg[0]];
        } else if (s_mk[t] > 0) {
            int tp = t - 1;
            while (tp > 0 && s_mk[tp] == 0) tp--;
            contrib += trans[s_tg[tp] * TT + s_tg[t]]
                     + logits[((size_t)b * SS + t) * TT + s_tg[t]];
            ridx = max(ridx, t);
        }
    }
    s_red[tid] = contrib;
    s_ridx[tid] = ridx;
    __syncthreads();
#pragma unroll
    for (int o = 128; o; o >>= 1) {
        if (tid < o) {
            s_red[tid] += s_red[tid + o];
            s_ridx[tid] = max(s_ridx[tid], s_ridx[tid + o]);
        }
        __syncthreads();
    }
    if (tid == 0) s_score = s_red[0] + endt[s_tg[s_ridx[0]]];

    // ---- tree combine: 4 levels of LINEAR 9x9 products with renorm ----
#pragma unroll
    for (int L = 0; L < 4; L++) {
        int nprod = 8 >> L, stride = 1 << L;
        if (w < nprod) {
            int a = (w * 2) * stride, bq = a + stride;
            float Bcol[TT];
#pragma unroll
            for (int k = 0; k < TT; k++) Bcol[k] = act ? sM[bq][k][lane] : 0.f;
            float C[TT];
            float mx = 1e-38f;
#pragma unroll
            for (int i = 0; i < TT; i++) {
                float s = 0.f;
#pragma unroll
                for (int k = 0; k < TT; k++)
                    s = fmaf(sM[a][i][k], Bcol[k], s);   // A broadcast-LDS
                C[i] = s;
                mx = fmaxf(mx, s);
            }
            float gm = 1e-38f;
#pragma unroll
            for (int k = 0; k < TT; k++)
                gm = fmaxf(gm, __shfl_sync(0xffffffffu, mx, k));
            float inv = __fdividef(1.f, gm);
            float addsc = sSc[bq] + __logf(gm);
            __syncwarp();
            if (act) {
#pragma unroll
                for (int i = 0; i < TT; i++) sM[a][i][lane] = C[i] * inv;
            }
            if (lane == 0) sSc[a] += addsc;
        }
        __syncthreads();
    }

    // ---- final: alpha0 (linear) @ M, logz, result ----
    if (w == 0) {
        float al = act ? (start[lane] + logits[(size_t)b * SS * TT + lane]) : -1e30f;
        float Ma = al;
#pragma unroll
        for (int o = 16; o; o >>= 1)
            Ma = fmaxf(Ma, __shfl_xor_sync(0xffffffffu, Ma, o));
        float av = __expf(al - Ma);            // 0 for inactive lanes
        float vj = 0.f;
#pragma unroll
        for (int i = 0; i < TT; i++) {
            float ai = __shfl_sync(0xffffffffu, av, i);
            vj = fmaf(ai, act ? sM[0][i][lane] : 0.f, vj);
        }
        float v = act ? (__logf(fmaxf(vj, 1e-38f)) + Ma + sSc[0] + endt[lane]) : -1e30f;
        float Mx = v;
#pragma unroll
        for (int o = 16; o; o >>= 1) Mx = fmaxf(Mx, __shfl_xor_sync(0xffffffffu, Mx, o));
        float e = __expf(v - Mx);
#pragma unroll
        for (int o = 16; o; o >>= 1) e += __shfl_xor_sync(0xffffffffu, e, o);
        if (lane == 0) g_res[b] = (Mx + __logf(e)) - s_score;
    }

    // ---- last block computes the mean (fused final) ----
    __shared__ unsigned s_ticket;
    __threadfence();
    __syncthreads();
    if (tid == 0) s_ticket = atomicAdd(&g_count, 1u);
    __syncthreads();
    if (s_ticket == BB - 1) {
        __threadfence();
        float vres = (tid < BB) ? g_res[tid] : 0.f;
        s_red[tid] = vres;
        __syncthreads();
#pragma unroll
        for (int o = 32; o; o >>= 1) {
            if (tid < o) s_red[tid] += s_red[tid + o];
            __syncthreads();
        }
        if (tid == 0) {
            out[0] = s_red[0] * (1.0f / 64.0f);
            g_count = 0;                        // reset for graph replay
        }
    }
}

// ---------------------------------------------------------------------------
extern "C" void kernel_launch(void* const* d_in, const int* in_sizes, int n_in,
                              void* d_out, int out_size)
{
    const float* input  = (const float*)d_in[0];
    const int*   labels = (const int*)  d_in[1];
    const int*   mask   = (const int*)  d_in[2];
    const float* W1     = (const float*)d_in[3];
    const float* b1     = (const float*)d_in[4];
    const float* W2     = (const float*)d_in[5];
    const float* b2     = (const float*)d_in[6];
    const float* start  = (const float*)d_in[7];
    const float* endt   = (const float*)d_in[8];
    const float* trans  = (const float*)d_in[9];

    float* out    = (float*)d_out;
    float* logits = out + 1;   // output layout: [loss, logits(B,S,T)]

    weff_kernel<<<DD / 8 + 1, 256>>>(W1, b1, W2, b2);
    gemv_chunk_kernel<<<BB * NC, 256>>>(input, logits, mask, trans);
    crf_combine_kernel<<<BB, 256>>>(logits, labels, mask, start, endt, trans, out);
}

// round 8
// speedup vs baseline: 1.4651x; 1.0007x over previous
#include <cuda_runtime.h>
#include <cuda_bf16.h>
#include <cstdint>

#define BB 64
#define SS 512
#define DD 1024
#define HH 1024
#define TT 9
#define NC 16        // time chunks per batch (chunk c = steps [32c, 32c+31], chunk0 = 1..31)

// Scratch (device globals; no allocation allowed)
__device__ float g_WeffT[TT * DD];     // SoA: [t][d]
__device__ float g_beff[TT];
__device__ float g_P[BB * NC * 81];    // per-chunk 9x9 log-domain composite
__device__ float g_res[BB];            // per-batch (logz - score)
__device__ unsigned g_count;           // combine completion ticket (resets to 0)

// ---------------------------------------------------------------------------
// Kernel 1: WeffT[t][d] = sum_h W1[d,h]*W2[h,t];  beff = b1@W2 + b2
// 33 blocks x 256 thr. Blocks 0..31: 32 d-rows each (warp = 4 rows, lanes
// split h -> coalesced). Block 32: bias row. W2 staged once per block via
// float4 (9 LDG.128/thread).
// ---------------------------------------------------------------------------
__global__ __launch_bounds__(256) void weff_kernel(
    const float* __restrict__ W1, const float* __restrict__ b1,
    const float* __restrict__ W2, const float* __restrict__ b2)
{
    __shared__ float sW2[HH * TT];     // 36 KB
    int tid = threadIdx.x;
    {
        float4* dst = (float4*)sW2;
        const float4* src4 = (const float4*)W2;
#pragma unroll
        for (int i = 0; i < 9; i++) dst[i * 256 + tid] = src4[i * 256 + tid];
    }
    __syncthreads();

    int w = tid >> 5, lane = tid & 31;
    bool isb = (blockIdx.x == 32);

    if (!isb) {
        int d0 = blockIdx.x * 32 + w * 4;
        const float* w1p = W1 + (size_t)d0 * HH;

        float acc[4][TT];
#pragma unroll
        for (int r = 0; r < 4; r++)
#pragma unroll
            for (int t = 0; t < TT; t++) acc[r][t] = 0.f;

#pragma unroll 2
        for (int k = 0; k < 32; k++) {
            int h = (k << 5) + lane;
            float a[4];
#pragma unroll
            for (int r = 0; r < 4; r++) a[r] = w1p[(size_t)r * HH + h];  // coalesced
            const float* w2r = sW2 + h * TT;     // lane stride 9 -> conflict-free
            float wv[TT];
#pragma unroll
            for (int t = 0; t < TT; t++) wv[t] = w2r[t];
#pragma unroll
            for (int r = 0; r < 4; r++)
#pragma unroll
                for (int t = 0; t < TT; t++)
                    acc[r][t] = fmaf(a[r], wv[t], acc[r][t]);
        }
#pragma unroll
        for (int r = 0; r < 4; r++)
#pragma unroll
            for (int t = 0; t < TT; t++)
#pragma unroll
                for (int o = 16; o; o >>= 1)
                    acc[r][t] += __shfl_xor_sync(0xffffffffu, acc[r][t], o);

        if (lane < 4) {
            int d = d0 + lane;
#pragma unroll
            for (int t = 0; t < TT; t++) g_WeffT[t * DD + d] = acc[lane][t];
        }
    } else if (w == 0) {
        float acc[TT];
#pragma unroll
        for (int t = 0; t < TT; t++) acc[t] = 0.f;
        for (int h = lane; h < HH; h += 32) {
            float a = b1[h];
            const float* r = sW2 + h * TT;
#pragma unroll
            for (int t = 0; t < TT; t++) acc[t] = fmaf(a, r[t], acc[t]);
        }
#pragma unroll
        for (int t = 0; t < TT; t++)
#pragma unroll
            for (int o = 16; o; o >>= 1)
                acc[t] += __shfl_xor_sync(0xffffffffu, acc[t], o);
        if (lane == 0) {
#pragma unroll
            for (int t = 0; t < TT; t++) g_beff[t] = acc[t] + b2[t];
        }
    }
}

// ---------------------------------------------------------------------------
// Kernel 2 (fused): logits tile + chunk composite (R6-proven; staging now f4).
// ---------------------------------------------------------------------------
__global__ __launch_bounds__(256) void gemv_chunk_kernel(
    const float* __restrict__ input, float* __restrict__ logits,
    const int* __restrict__ mask, const float* __restrict__ trans)
{
    __shared__ float sWt[TT * DD];       // 36 KB, [t][d]
    __shared__ float s_lg[32][TT];       // this block's 32 logit rows
    __shared__ int   s_mk[32];
    __shared__ float sM[8][TT][12];      // per-warp composites (padded)
    __shared__ float sSc[8];             // per-warp log-scales

    int tid = threadIdx.x;
    {
        float4* dst = (float4*)sWt;
        const float4* src4 = (const float4*)g_WeffT;
#pragma unroll
        for (int i = 0; i < 9; i++) dst[i * 256 + tid] = src4[i * 256 + tid];
    }

    int b = blockIdx.x >> 4;             // batch
    int c = blockIdx.x & 15;             // chunk
    if (tid < 32) s_mk[tid] = mask[(size_t)b * SS + c * 32 + tid];
    __syncthreads();

    int w = tid >> 5, lane = tid & 31;
    int rowbase = blockIdx.x * 32 + w * 4;
    const float* ip = input + (size_t)rowbase * DD;

    float acc[4][TT];
#pragma unroll
    for (int r = 0; r < 4; r++)
#pragma unroll
        for (int t = 0; t < TT; t++) acc[r][t] = 0.f;

#pragma unroll 2
    for (int k = 0; k < 32; k++) {
        int d = (k << 5) + lane;
        float x[4];
#pragma unroll
        for (int r = 0; r < 4; r++) x[r] = ip[(size_t)r * DD + d];  // coalesced
        float wv[TT];
#pragma unroll
        for (int t = 0; t < TT; t++) wv[t] = sWt[t * DD + d];       // stride-1 LDS
#pragma unroll
        for (int r = 0; r < 4; r++)
#pragma unroll
            for (int t = 0; t < TT; t++)
                acc[r][t] = fmaf(x[r], wv[t], acc[r][t]);
    }

#pragma unroll
    for (int r = 0; r < 4; r++)
#pragma unroll
        for (int t = 0; t < TT; t++)
#pragma unroll
            for (int o = 16; o; o >>= 1)
                acc[r][t] += __shfl_xor_sync(0xffffffffu, acc[r][t], o);

    if (lane < 4) {
        int rl = w * 4 + lane;
        float* o = logits + (size_t)(rowbase + lane) * TT;
#pragma unroll
        for (int t = 0; t < TT; t++) {
            float v = acc[lane][t] + g_beff[t];
            o[t] = v;
            s_lg[rl][t] = v;
        }
    }
    __syncthreads();

    // ================= chunk composite =================
    bool act = (lane < TT);
    float E[TT];
#pragma unroll
    for (int k = 0; k < TT; k++)
        E[k] = act ? __expf(trans[k * TT + lane]) : 0.f;

    int ls0 = w * 4;
    int sfirst = (c == 0 && w == 0) ? 1 : 0;     // skip global t = 0

    float R[TT];
    {   // init from first step (or identity if masked)
        int ls = ls0 + sfirst;
        bool mm = (s_mk[ls] != 0);
        float eem = act ? __expf(s_lg[ls][lane]) : 0.f;
#pragma unroll
        for (int i = 0; i < TT; i++)
            R[i] = mm ? E[i] * eem : ((act && i == lane) ? 1.f : 0.f);
    }
#pragma unroll
    for (int q = 1; q < 4; q++) {
        int ls = ls0 + ((sfirst) ? (q + 1) : q);
        if (ls >= ls0 + 4) break;                // only when sfirst==1: 3 steps
        if (s_mk[ls] != 0) {
            float eem = act ? __expf(s_lg[ls][lane]) : 0.f;
#pragma unroll
            for (int i = 0; i < TT; i++) {
                float v = R[i];
                float sum = 0.f;
#pragma unroll
                for (int k = 0; k < TT; k++)
                    sum = fmaf(__shfl_sync(0xffffffffu, v, k), E[k], sum);
                R[i] = sum * eem;
            }
        }
    }
    // per-warp renorm + store
    {
        float mx = 1e-38f;
#pragma unroll
        for (int i = 0; i < TT; i++) mx = fmaxf(mx, R[i]);
        float gm = 1e-38f;
#pragma unroll
        for (int k = 0; k < TT; k++)
            gm = fmaxf(gm, __shfl_sync(0xffffffffu, mx, k));
        float inv = __fdividef(1.f, gm);
        if (act) {
#pragma unroll
            for (int i = 0; i < TT; i++) sM[w][i][lane] = R[i] * inv;
        }
        if (lane == 0) sSc[w] = __logf(gm);
    }
    __syncthreads();

    // tree: 3 levels of linear 9x9 products (A earlier, B later)
#pragma unroll
    for (int L = 0; L < 3; L++) {
        int stride = 1 << L, npr = 4 >> L;
        if (w < npr) {
            int a = 2 * stride * w, bq = a + stride;
            float Bcol[TT];
#pragma unroll
            for (int k = 0; k < TT; k++) Bcol[k] = act ? sM[bq][k][lane] : 0.f;
            float C[TT];
            float mx = 1e-38f;
#pragma unroll
            for (int i = 0; i < TT; i++) {
                float s = 0.f;
#pragma unroll
                for (int k = 0; k < TT; k++)
                    s = fmaf(sM[a][i][k], Bcol[k], s);   // A broadcast-LDS
                C[i] = s;
                mx = fmaxf(mx, s);
            }
            float gm = 1e-38f;
#pragma unroll
            for (int k = 0; k < TT; k++)
                gm = fmaxf(gm, __shfl_sync(0xffffffffu, mx, k));
            float inv = __fdividef(1.f, gm);
            float addsc = sSc[bq] + __logf(gm);
            __syncwarp();
            if (act) {
#pragma unroll
                for (int i = 0; i < TT; i++) sM[a][i][lane] = C[i] * inv;
            }
            if (lane == 0) sSc[a] += addsc;
        }
        __syncthreads();
    }

    if (w == 0 && act) {
        float sc = sSc[0];
        float* Pp = g_P + (size_t)blockIdx.x * 81;
#pragma unroll
        for (int i = 0; i < TT; i++)
            Pp[i * TT + lane] = __logf(fmaxf(sM[0][i][lane], 1e-38f)) + sc;
    }
}

// ---------------------------------------------------------------------------
// Kernel 3: per-batch combine, LINEAR-domain tree + fused final reduce.
// ---------------------------------------------------------------------------
__global__ __launch_bounds__(256) void crf_combine_kernel(
    const float* __restrict__ logits, const int* __restrict__ labels,
    const int* __restrict__ mask, const float* __restrict__ start,
    const float* __restrict__ endt, const float* __restrict__ trans,
    float* __restrict__ out)
{
    __shared__ float sM[NC][TT][12];   // linear matrices (padded cols)
    __shared__ float sSc[NC];          // per-matrix log scales
    __shared__ int   s_mk[SS];
    __shared__ int   s_tg[SS];
    __shared__ float s_red[256];
    __shared__ int   s_ridx[256];
    __shared__ float s_score;

    int b = blockIdx.x, tid = threadIdx.x;
    int w = tid >> 5, lane = tid & 31;
    bool act = (lane < TT);

    for (int i = tid; i < SS; i += 256) {
        s_mk[i] = mask[(size_t)b * SS + i];
        s_tg[i] = labels[(size_t)b * SS + i];
    }

    // ---- load chunk matrices, convert to linear with per-matrix renorm ----
    const float* Pb = g_P + (size_t)b * NC * 81;
#pragma unroll
    for (int h = 0; h < 2; h++) {
        int m = w * 2 + h;
        const float* Pm = Pb + m * 81;
        float col[TT];
        float mx = -1e30f;
#pragma unroll
        for (int i = 0; i < TT; i++) {
            col[i] = act ? Pm[i * TT + lane] : -1e30f;
            mx = fmaxf(mx, col[i]);
        }
        float gm = mx;
#pragma unroll
        for (int o = 16; o; o >>= 1)
            gm = fmaxf(gm, __shfl_xor_sync(0xffffffffu, gm, o));
        if (act) {
#pragma unroll
            for (int i = 0; i < TT; i++) sM[m][i][lane] = __expf(col[i] - gm);
        }
        if (lane == 0) sSc[m] = gm;
    }
    __syncthreads();

    // ---- numerator partial + last-masked-index (each thread: t, t+256) ----
    float contrib = 0.f;
    int ridx = 0;
#pragma unroll
    for (int h = 0; h < 2; h++) {
        int t = tid + h * 256;
        if (t == 0) {
            contrib += start[s_tg[0]] + logits[(size_t)b * SS * TT + s_tg[0]];
        } else if (s_mk[t] > 0) {
            int tp = t - 1;
            while (tp > 0 && s_mk[tp] == 0) tp--;
            contrib += trans[s_tg[tp] * TT + s_tg[t]]
                     + logits[((size_t)b * SS + t) * TT + s_tg[t]];
            ridx = max(ridx, t);
        }
    }
    s_red[tid] = contrib;
    s_ridx[tid] = ridx;
    __syncthreads();
#pragma unroll
    for (int o = 128; o; o >>= 1) {
        if (tid < o) {
            s_red[tid] += s_red[tid + o];
            s_ridx[tid] = max(s_ridx[tid], s_ridx[tid + o]);
        }
        __syncthreads();
    }
    if (tid == 0) s_score = s_red[0] + endt[s_tg[s_ridx[0]]];

    // ---- tree combine: 4 levels of LINEAR 9x9 products with renorm ----
#pragma unroll
    for (int L = 0; L < 4; L++) {
        int nprod = 8 >> L, stride = 1 << L;
        if (w < nprod) {
            int a = (w * 2) * stride, bq = a + stride;
            float Bcol[TT];
#pragma unroll
            for (int k = 0; k < TT; k++) Bcol[k] = act ? sM[bq][k][lane] : 0.f;
            float C[TT];
            float mx = 1e-38f;
#pragma unroll
            for (int i = 0; i < TT; i++) {
                float s = 0.f;
#pragma unroll
                for (int k = 0; k < TT; k++)
                    s = fmaf(sM[a][i][k], Bcol[k], s);   // A broadcast-LDS
                C[i] = s;
                mx = fmaxf(mx, s);
            }
            float gm = 1e-38f;
#pragma unroll
            for (int k = 0; k < TT; k++)
                gm = fmaxf(gm, __shfl_sync(0xffffffffu, mx, k));
            float inv = __fdividef(1.f, gm);
            float addsc = sSc[bq] + __logf(gm);
            __syncwarp();
            if (act) {
#pragma unroll
                for (int i = 0; i < TT; i++) sM[a][i][lane] = C[i] * inv;
            }
            if (lane == 0) sSc[a] += addsc;
        }
        __syncthreads();
    }

    // ---- final: alpha0 (linear) @ M, logz, result ----
    if (w == 0) {
        float al = act ? (start[lane] + logits[(size_t)b * SS * TT + lane]) : -1e30f;
        float Ma = al;
#pragma unroll
        for (int o = 16; o; o >>= 1)
            Ma = fmaxf(Ma, __shfl_xor_sync(0xffffffffu, Ma, o));
        float av = __expf(al - Ma);            // 0 for inactive lanes
        float vj = 0.f;
#pragma unroll
        for (int i = 0; i < TT; i++) {
            float ai = __shfl_sync(0xffffffffu, av, i);
            vj = fmaf(ai, act ? sM[0][i][lane] : 0.f, vj);
        }
        float v = act ? (__logf(fmaxf(vj, 1e-38f)) + Ma + sSc[0] + endt[lane]) : -1e30f;
        float Mx = v;
#pragma unroll
        for (int o = 16; o; o >>= 1) Mx = fmaxf(Mx, __shfl_xor_sync(0xffffffffu, Mx, o));
        float e = __expf(v - Mx);
#pragma unroll
        for (int o = 16; o; o >>= 1) e += __shfl_xor_sync(0xffffffffu, e, o);
        if (lane == 0) g_res[b] = (Mx + __logf(e)) - s_score;
    }

    // ---- last block computes the mean (fused final) ----
    __shared__ unsigned s_ticket;
    __threadfence();
    __syncthreads();
    if (tid == 0) s_ticket = atomicAdd(&g_count, 1u);
    __syncthreads();
    if (s_ticket == BB - 1) {
        __threadfence();
        float vres = (tid < BB) ? g_res[tid] : 0.f;
        s_red[tid] = vres;
        __syncthreads();
#pragma unroll
        for (int o = 32; o; o >>= 1) {
            if (tid < o) s_red[tid] += s_red[tid + o];
            __syncthreads();
        }
        if (tid == 0) {
            out[0] = s_red[0] * (1.0f / 64.0f);
            g_count = 0;                        // reset for graph replay
        }
    }
}

// ---------------------------------------------------------------------------
extern "C" void kernel_launch(void* const* d_in, const int* in_sizes, int n_in,
                              void* d_out, int out_size)
{
    const float* input  = (const float*)d_in[0];
    const int*   labels = (const int*)  d_in[1];
    const int*   mask   = (const int*)  d_in[2];
    const float* W1     = (const float*)d_in[3];
    const float* b1     = (const float*)d_in[4];
    const float* W2     = (const float*)d_in[5];
    const float* b2     = (const float*)d_in[6];
    const float* start  = (const float*)d_in[7];
    const float* endt   = (const float*)d_in[8];
    const float* trans  = (const float*)d_in[9];

    float* out    = (float*)d_out;
    float* logits = out + 1;   // output layout: [loss, logits(B,S,T)]

    weff_kernel<<<33, 256>>>(W1, b1, W2, b2);
    gemv_chunk_kernel<<<BB * NC, 256>>>(input, logits, mask, trans);
    crf_combine_kernel<<<BB, 256>>>(logits, labels, mask, start, endt, trans, out);
}

// round 9
// speedup vs baseline: 1.4989x; 1.0230x over previous
#include <cuda_runtime.h>
#include <cuda_bf16.h>
#include <cstdint>

#define BB 64
#define SS 512
#define DD 1024
#define HH 1024
#define TT 9
#define NC 16        // time chunks per batch (chunk c = steps [32c, 32c+31], chunk0 = 1..31)
#define HS 4         // h-splits for weff
#define HSL (HH / HS)

// Scratch (device globals; no allocation allowed)
__device__ float g_Wpart[HS * TT * DD];  // per-split partial WeffT, SoA [t][d]
__device__ float g_beffp[HS * TT];       // per-split partial beff
__device__ float g_P[BB * NC * 81];      // per-chunk 9x9 log-domain composite
__device__ float g_res[BB];              // per-batch (logz - score)
__device__ unsigned g_count;             // combine completion ticket (resets to 0)

// ---------------------------------------------------------------------------
// Kernel 1: split-K Weff partials.
// grid 132: blocks 0..127 = (dg = bx>>2, hs = bx&3): 32 d-rows x 256 h.
//           blocks 128..131 = bias partial for h-split (bx-128).
// Each block stages a 9 KB W2 slice; mainloop fully unrolled (32 LDGs in
// flight per warp) -> short latency chain, 128 blocks spread over SMs.
// ---------------------------------------------------------------------------
__global__ __launch_bounds__(256) void weff_part_kernel(
    const float* __restrict__ W1, const float* __restrict__ b1,
    const float* __restrict__ W2, const float* __restrict__ b2)
{
    __shared__ float sW2[HSL * TT];      // 9 KB slice
    int tid = threadIdx.x;
    int bx = blockIdx.x;
    int hs = (bx < 128) ? (bx & 3) : (bx - 128);
    int h0 = hs * HSL;

    {   // stage slice: 2304 floats = 576 float4
        const float4* src4 = (const float4*)(W2 + (size_t)h0 * TT);
        float4* dst = (float4*)sW2;
        for (int i = tid; i < 576; i += 256) dst[i] = src4[i];
    }
    __syncthreads();

    int w = tid >> 5, lane = tid & 31;

    if (bx < 128) {
        int dg = bx >> 2;
        int d0 = dg * 32 + w * 4;
        const float* w1p = W1 + (size_t)d0 * HH + h0;

        float acc[4][TT];
#pragma unroll
        for (int r = 0; r < 4; r++)
#pragma unroll
            for (int t = 0; t < TT; t++) acc[r][t] = 0.f;

#pragma unroll
        for (int k = 0; k < 8; k++) {           // FULL unroll: 32 LDGs in flight
            int h = (k << 5) + lane;
            float a[4];
#pragma unroll
            for (int r = 0; r < 4; r++) a[r] = w1p[(size_t)r * HH + h];  // coalesced
            const float* w2r = sW2 + h * TT;
            float wv[TT];
#pragma unroll
            for (int t = 0; t < TT; t++) wv[t] = w2r[t];
#pragma unroll
            for (int r = 0; r < 4; r++)
#pragma unroll
                for (int t = 0; t < TT; t++)
                    acc[r][t] = fmaf(a[r], wv[t], acc[r][t]);
        }
#pragma unroll
        for (int r = 0; r < 4; r++)
#pragma unroll
            for (int t = 0; t < TT; t++)
#pragma unroll
                for (int o = 16; o; o >>= 1)
                    acc[r][t] += __shfl_xor_sync(0xffffffffu, acc[r][t], o);

        if (lane < 4) {
            int d = d0 + lane;
            float* dst = g_Wpart + (size_t)hs * TT * DD;
#pragma unroll
            for (int t = 0; t < TT; t++) dst[t * DD + d] = acc[lane][t];
        }
    } else if (w == 0) {
        float acc[TT];
#pragma unroll
        for (int t = 0; t < TT; t++) acc[t] = 0.f;
#pragma unroll
        for (int k = 0; k < 8; k++) {
            int h = (k << 5) + lane;
            float a = b1[h0 + h];
            const float* r = sW2 + h * TT;
#pragma unroll
            for (int t = 0; t < TT; t++) acc[t] = fmaf(a, r[t], acc[t]);
        }
#pragma unroll
        for (int t = 0; t < TT; t++)
#pragma unroll
            for (int o = 16; o; o >>= 1)
                acc[t] += __shfl_xor_sync(0xffffffffu, acc[t], o);
        if (lane == 0) {
#pragma unroll
            for (int t = 0; t < TT; t++)
                g_beffp[hs * TT + t] = acc[t] + ((hs == 0) ? b2[t] : 0.f);
        }
    }
}

// ---------------------------------------------------------------------------
// Kernel 2 (fused): logits tile + chunk composite. Staging sums the 4 Weff
// partials in fixed order (deterministic); beff assembled into smem likewise.
// ---------------------------------------------------------------------------
__global__ __launch_bounds__(256) void gemv_chunk_kernel(
    const float* __restrict__ input, float* __restrict__ logits,
    const int* __restrict__ mask, const float* __restrict__ trans)
{
    __shared__ float sWt[TT * DD];       // 36 KB, [t][d]
    __shared__ float s_be[TT];
    __shared__ float s_lg[32][TT];       // this block's 32 logit rows
    __shared__ int   s_mk[32];
    __shared__ float sM[8][TT][12];      // per-warp composites (padded)
    __shared__ float sSc[8];             // per-warp log-scales

    int tid = threadIdx.x;
    {   // stage Weff = p0+p1+p2+p3 (L2-broadcast across all 1024 blocks)
        const float4* p0 = (const float4*)(g_Wpart + 0 * TT * DD);
        const float4* p1 = (const float4*)(g_Wpart + 1 * TT * DD);
        const float4* p2 = (const float4*)(g_Wpart + 2 * TT * DD);
        const float4* p3 = (const float4*)(g_Wpart + 3 * TT * DD);
        float4* dst = (float4*)sWt;
#pragma unroll
        for (int i = 0; i < 9; i++) {
            int idx = i * 256 + tid;
            float4 a = p0[idx], b4 = p1[idx], c4 = p2[idx], d4 = p3[idx];
            dst[idx] = make_float4(a.x + b4.x + c4.x + d4.x,
                                   a.y + b4.y + c4.y + d4.y,
                                   a.z + b4.z + c4.z + d4.z,
                                   a.w + b4.w + c4.w + d4.w);
        }
    }
    if (tid < TT)
        s_be[tid] = g_beffp[0 * TT + tid] + g_beffp[1 * TT + tid]
                  + g_beffp[2 * TT + tid] + g_beffp[3 * TT + tid];

    int b = blockIdx.x >> 4;             // batch
    int c = blockIdx.x & 15;             // chunk
    if (tid < 32) s_mk[tid] = mask[(size_t)b * SS + c * 32 + tid];
    __syncthreads();

    int w = tid >> 5, lane = tid & 31;
    int rowbase = blockIdx.x * 32 + w * 4;
    const float* ip = input + (size_t)rowbase * DD;

    float acc[4][TT];
#pragma unroll
    for (int r = 0; r < 4; r++)
#pragma unroll
        for (int t = 0; t < TT; t++) acc[r][t] = 0.f;

#pragma unroll 2
    for (int k = 0; k < 32; k++) {
        int d = (k << 5) + lane;
        float x[4];
#pragma unroll
        for (int r = 0; r < 4; r++) x[r] = ip[(size_t)r * DD + d];  // coalesced
        float wv[TT];
#pragma unroll
        for (int t = 0; t < TT; t++) wv[t] = sWt[t * DD + d];       // stride-1 LDS
#pragma unroll
        for (int r = 0; r < 4; r++)
#pragma unroll
            for (int t = 0; t < TT; t++)
                acc[r][t] = fmaf(x[r], wv[t], acc[r][t]);
    }

#pragma unroll
    for (int r = 0; r < 4; r++)
#pragma unroll
        for (int t = 0; t < TT; t++)
#pragma unroll
            for (int o = 16; o; o >>= 1)
                acc[r][t] += __shfl_xor_sync(0xffffffffu, acc[r][t], o);

    if (lane < 4) {
        int rl = w * 4 + lane;
        float* o = logits + (size_t)(rowbase + lane) * TT;
#pragma unroll
        for (int t = 0; t < TT; t++) {
            float v = acc[lane][t] + s_be[t];
            o[t] = v;
            s_lg[rl][t] = v;
        }
    }
    __syncthreads();

    // ================= chunk composite =================
    bool act = (lane < TT);
    float E[TT];
#pragma unroll
    for (int k = 0; k < TT; k++)
        E[k] = act ? __expf(trans[k * TT + lane]) : 0.f;

    int ls0 = w * 4;
    int sfirst = (c == 0 && w == 0) ? 1 : 0;     // skip global t = 0

    float R[TT];
    {   // init from first step (or identity if masked)
        int ls = ls0 + sfirst;
        bool mm = (s_mk[ls] != 0);
        float eem = act ? __expf(s_lg[ls][lane]) : 0.f;
#pragma unroll
        for (int i = 0; i < TT; i++)
            R[i] = mm ? E[i] * eem : ((act && i == lane) ? 1.f : 0.f);
    }
#pragma unroll
    for (int q = 1; q < 4; q++) {
        int ls = ls0 + ((sfirst) ? (q + 1) : q);
        if (ls >= ls0 + 4) break;                // only when sfirst==1: 3 steps
        if (s_mk[ls] != 0) {
            float eem = act ? __expf(s_lg[ls][lane]) : 0.f;
#pragma unroll
            for (int i = 0; i < TT; i++) {
                float v = R[i];
                float sum = 0.f;
#pragma unroll
                for (int k = 0; k < TT; k++)
                    sum = fmaf(__shfl_sync(0xffffffffu, v, k), E[k], sum);
                R[i] = sum * eem;
            }
        }
    }
    // per-warp renorm + store
    {
        float mx = 1e-38f;
#pragma unroll
        for (int i = 0; i < TT; i++) mx = fmaxf(mx, R[i]);
        float gm = 1e-38f;
#pragma unroll
        for (int k = 0; k < TT; k++)
            gm = fmaxf(gm, __shfl_sync(0xffffffffu, mx, k));
        float inv = __fdividef(1.f, gm);
        if (act) {
#pragma unroll
            for (int i = 0; i < TT; i++) sM[w][i][lane] = R[i] * inv;
        }
        if (lane == 0) sSc[w] = __logf(gm);
    }
    __syncthreads();

    // tree: 3 levels of linear 9x9 products (A earlier, B later)
#pragma unroll
    for (int L = 0; L < 3; L++) {
        int stride = 1 << L, npr = 4 >> L;
        if (w < npr) {
            int a = 2 * stride * w, bq = a + stride;
            float Bcol[TT];
#pragma unroll
            for (int k = 0; k < TT; k++) Bcol[k] = act ? sM[bq][k][lane] : 0.f;
            float C[TT];
            float mx = 1e-38f;
#pragma unroll
            for (int i = 0; i < TT; i++) {
                float s = 0.f;
#pragma unroll
                for (int k = 0; k < TT; k++)
                    s = fmaf(sM[a][i][k], Bcol[k], s);   // A broadcast-LDS
                C[i] = s;
                mx = fmaxf(mx, s);
            }
            float gm = 1e-38f;
#pragma unroll
            for (int k = 0; k < TT; k++)
                gm = fmaxf(gm, __shfl_sync(0xffffffffu, mx, k));
            float inv = __fdividef(1.f, gm);
            float addsc = sSc[bq] + __logf(gm);
            __syncwarp();
            if (act) {
#pragma unroll
                for (int i = 0; i < TT; i++) sM[a][i][lane] = C[i] * inv;
            }
            if (lane == 0) sSc[a] += addsc;
        }
        __syncthreads();
    }

    if (w == 0 && act) {
        float sc = sSc[0];
        float* Pp = g_P + (size_t)blockIdx.x * 81;
#pragma unroll
        for (int i = 0; i < TT; i++)
            Pp[i * TT + lane] = __logf(fmaxf(sM[0][i][lane], 1e-38f)) + sc;
    }
}

// ---------------------------------------------------------------------------
// Kernel 3: per-batch combine, LINEAR-domain tree + fused final reduce.
// ---------------------------------------------------------------------------
__global__ __launch_bounds__(256) void crf_combine_kernel(
    const float* __restrict__ logits, const int* __restrict__ labels,
    const int* __restrict__ mask, const float* __restrict__ start,
    const float* __restrict__ endt, const float* __restrict__ trans,
    float* __restrict__ out)
{
    __shared__ float sM[NC][TT][12];   // linear matrices (padded cols)
    __shared__ float sSc[NC];          // per-matrix log scales
    __shared__ int   s_mk[SS];
    __shared__ int   s_tg[SS];
    __shared__ float s_red[256];
    __shared__ int   s_ridx[256];
    __shared__ float s_score;

    int b = blockIdx.x, tid = threadIdx.x;
    int w = tid >> 5, lane = tid & 31;
    bool act = (lane < TT);

    for (int i = tid; i < SS; i += 256) {
        s_mk[i] = mask[(size_t)b * SS + i];
        s_tg[i] = labels[(size_t)b * SS + i];
    }

    // ---- load chunk matrices, convert to linear with per-matrix renorm ----
    const float* Pb = g_P + (size_t)b * NC * 81;
#pragma unroll
    for (int h = 0; h < 2; h++) {
        int m = w * 2 + h;
        const float* Pm = Pb + m * 81;
        float col[TT];
        float mx = -1e30f;
#pragma unroll
        for (int i = 0; i < TT; i++) {
            col[i] = act ? Pm[i * TT + lane] : -1e30f;
            mx = fmaxf(mx, col[i]);
        }
        float gm = mx;
#pragma unroll
        for (int o = 16; o; o >>= 1)
            gm = fmaxf(gm, __shfl_xor_sync(0xffffffffu, gm, o));
        if (act) {
#pragma unroll
            for (int i = 0; i < TT; i++) sM[m][i][lane] = __expf(col[i] - gm);
        }
        if (lane == 0) sSc[m] = gm;
    }
    __syncthreads();

    // ---- numerator partial + last-masked-index (each thread: t, t+256) ----
    float contrib = 0.f;
    int ridx = 0;
#pragma unroll
    for (int h = 0; h < 2; h++) {
        int t = tid + h * 256;
        if (t == 0) {
            contrib += start[s_tg[0]] + logits[(size_t)b * SS * TT + s_tg[0]];
        } else if (s_mk[t] > 0) {
            int tp = t - 1;
            while (tp > 0 && s_mk[tp] == 0) tp--;
            contrib += trans[s_tg[tp] * TT + s_tg[t]]
                     + logits[((size_t)b * SS + t) * TT + s_tg[t]];
            ridx = max(ridx, t);
        }
    }
    s_red[tid] = contrib;
    s_ridx[tid] = ridx;
    __syncthreads();
#pragma unroll
    for (int o = 128; o; o >>= 1) {
        if (tid < o) {
            s_red[tid] += s_red[tid + o];
            s_ridx[tid] = max(s_ridx[tid], s_ridx[tid + o]);
        }
        __syncthreads();
    }
    if (tid == 0) s_score = s_red[0] + endt[s_tg[s_ridx[0]]];

    // ---- tree combine: 4 levels of LINEAR 9x9 products with renorm ----
#pragma unroll
    for (int L = 0; L < 4; L++) {
        int nprod = 8 >> L, stride = 1 << L;
        if (w < nprod) {
            int a = (w * 2) * stride, bq = a + stride;
            float Bcol[TT];
#pragma unroll
            for (int k = 0; k < TT; k++) Bcol[k] = act ? sM[bq][k][lane] : 0.f;
            float C[TT];
            float mx = 1e-38f;
#pragma unroll
            for (int i = 0; i < TT; i++) {
                float s = 0.f;
#pragma unroll
                for (int k = 0; k < TT; k++)
                    s = fmaf(sM[a][i][k], Bcol[k], s);   // A broadcast-LDS
                C[i] = s;
                mx = fmaxf(mx, s);
            }
            float gm = 1e-38f;
#pragma unroll
            for (int k = 0; k < TT; k++)
                gm = fmaxf(gm, __shfl_sync(0xffffffffu, mx, k));
            float inv = __fdividef(1.f, gm);
            float addsc = sSc[bq] + __logf(gm);
            __syncwarp();
            if (act) {
#pragma unroll
                for (int i = 0; i < TT; i++) sM[a][i][lane] = C[i] * inv;
            }
            if (lane == 0) sSc[a] += addsc;
        }
        __syncthreads();
    }

    // ---- final: alpha0 (linear) @ M, logz, result ----
    if (w == 0) {
        float al = act ? (start[lane] + logits[(size_t)b * SS * TT + lane]) : -1e30f;
        float Ma = al;
#pragma unroll
        for (int o = 16; o; o >>= 1)
            Ma = fmaxf(Ma, __shfl_xor_sync(0xffffffffu, Ma, o));
        float av = __expf(al - Ma);            // 0 for inactive lanes
        float vj = 0.f;
#pragma unroll
        for (int i = 0; i < TT; i++) {
            float ai = __shfl_sync(0xffffffffu, av, i);
            vj = fmaf(ai, act ? sM[0][i][lane] : 0.f, vj);
        }
        float v = act ? (__logf(fmaxf(vj, 1e-38f)) + Ma + sSc[0] + endt[lane]) : -1e30f;
        float Mx = v;
#pragma unroll
        for (int o = 16; o; o >>= 1) Mx = fmaxf(Mx, __shfl_xor_sync(0xffffffffu, Mx, o));
        float e = __expf(v - Mx);
#pragma unroll
        for (int o = 16; o; o >>= 1) e += __shfl_xor_sync(0xffffffffu, e, o);
        if (lane == 0) g_res[b] = (Mx + __logf(e)) - s_score;
    }

    // ---- last block computes the mean (fused final) ----
    __shared__ unsigned s_ticket;
    __threadfence();
    __syncthreads();
    if (tid == 0) s_ticket = atomicAdd(&g_count, 1u);
    __syncthreads();
    if (s_ticket == BB - 1) {
        __threadfence();
        float vres = (tid < BB) ? g_res[tid] : 0.f;
        s_red[tid] = vres;
        __syncthreads();
#pragma unroll
        for (int o = 32; o; o >>= 1) {
            if (tid < o) s_red[tid] += s_red[tid + o];
            __syncthreads();
        }
        if (tid == 0) {
            out[0] = s_red[0] * (1.0f / 64.0f);
            g_count = 0;                        // reset for graph replay
        }
    }
}

// ---------------------------------------------------------------------------
extern "C" void kernel_launch(void* const* d_in, const int* in_sizes, int n_in,
                              void* d_out, int out_size)
{
    const float* input  = (const float*)d_in[0];
    const int*   labels = (const int*)  d_in[1];
    const int*   mask   = (const int*)  d_in[2];
    const float* W1     = (const float*)d_in[3];
    const float* b1     = (const float*)d_in[4];
    const float* W2     = (const float*)d_in[5];
    const float* b2     = (const float*)d_in[6];
    const float* start  = (const float*)d_in[7];
    const float* endt   = (const float*)d_in[8];
    const float* trans  = (const float*)d_in[9];

    float* out    = (float*)d_out;
    float* logits = out + 1;   // output layout: [loss, logits(B,S,T)]

    weff_part_kernel<<<132, 256>>>(W1, b1, W2, b2);
    gemv_chunk_kernel<<<BB * NC, 256>>>(input, logits, mask, trans);
    crf_combine_kernel<<<BB, 256>>>(logits, labels, mask, start, endt, trans, out);
}